// round 1
// baseline (speedup 1.0000x reference)
#include <cuda_runtime.h>

// ---------------------------------------------------------------------------
// dilate_block: sparse-conv residual pyramid
//   block1 (N=80000, 32->64) -> pool (K=27, stride2) -> block2, block3 (M rows)
//   -> concat(x1,x2,x3) @ down_w
// Round 1: fp32 FFMA gather-GEMM kernels, BN fused into the following gather.
// ---------------------------------------------------------------------------

static constexpr int ROWS = 16;          // output rows per block
static constexpr int MAXR = 640000;      // hard bound on M (<= 8 * N_VOX)
static constexpr int MAXBLK = (MAXR + ROWS - 1) / ROWS;

// Scratch (allocation-free rule: static __device__ arrays)
__device__ float g_A [MAXR * 64];
__device__ float g_B [MAXR * 64];
__device__ float g_C [MAXR * 64];
__device__ float g_X1[MAXR * 64];
__device__ float g_X2[MAXR * 64];
__device__ float g_X3[MAXR * 64];
__device__ float g_pS[MAXBLK * 64];
__device__ float g_pQ[MAXBLK * 64];
__device__ float g_stats[4 * 128];       // 4 slots of [mean[64], rstd[64]]

// ---------------------------------------------------------------------------
// Gather-GEMM sparse conv.
//   out[n, co] = sum_k sum_ci  f(in[nbr[k,n], ci]) * W[k, ci, co]
// f() optionally applies BatchNorm (mean/rstd) + LeakyReLU(0.01) on the fly.
// Missing neighbor (index == nIn) contributes zero (post-activation zero,
// matching the reference's zero row appended after bn_act).
// Also emits per-block column partial sums / sums-of-squares of the raw
// output (for the next BN), deterministically (fixed-order reductions).
// ---------------------------------------------------------------------------
template <int CIN, int K>
__global__ void __launch_bounds__(128)
conv_kernel(const float* __restrict__ in, int nIn,
            const int* __restrict__ nbr, int nOut,
            const float* __restrict__ W,
            const float* __restrict__ bnstats,      // [mean[64], rstd[64]] or null
            float* __restrict__ out,
            float* __restrict__ pSum, float* __restrict__ pSq)
{
    __shared__ __align__(16) float sh[ROWS][CIN];
    __shared__ float s_mean[64];
    __shared__ float s_rstd[64];
    __shared__ float red[2][2][64];

    const int t  = threadIdx.x;
    const int co = t & 63;
    const int rh = t >> 6;                  // 0/1: which 8-row half this thread owns
    const int rowBase = blockIdx.x * ROWS;
    const bool useBN = (bnstats != nullptr);

    if (useBN && t < 64) { s_mean[t] = bnstats[t]; s_rstd[t] = bnstats[64 + t]; }

    float acc[8];
#pragma unroll
    for (int r = 0; r < 8; ++r) acc[r] = 0.f;

    for (int k = 0; k < K; ++k) {
        __syncthreads();   // protect sh reuse from previous k
        // gather ROWS rows of CIN floats (vectorized), with fused BN+act
#pragma unroll
        for (int i4 = t; i4 < ROWS * CIN / 4; i4 += 128) {
            const int r  = (i4 * 4) / CIN;
            const int ci = (i4 * 4) % CIN;
            const int orow = rowBase + r;
            float4 v = make_float4(0.f, 0.f, 0.f, 0.f);
            if (orow < nOut) {
                const int j = nbr[(long long)k * nOut + orow];
                if (j < nIn) {
                    v = *reinterpret_cast<const float4*>(&in[(long long)j * CIN + ci]);
                    if (useBN) {
                        v.x = (v.x - s_mean[ci + 0]) * s_rstd[ci + 0];
                        v.y = (v.y - s_mean[ci + 1]) * s_rstd[ci + 1];
                        v.z = (v.z - s_mean[ci + 2]) * s_rstd[ci + 2];
                        v.w = (v.w - s_mean[ci + 3]) * s_rstd[ci + 3];
                        v.x = v.x > 0.f ? v.x : 0.01f * v.x;
                        v.y = v.y > 0.f ? v.y : 0.01f * v.y;
                        v.z = v.z > 0.f ? v.z : 0.01f * v.z;
                        v.w = v.w > 0.f ? v.w : 0.01f * v.w;
                    }
                }
            }
            *reinterpret_cast<float4*>(&sh[r][ci]) = v;
        }
        __syncthreads();

        const float* Wk = W + k * CIN * 64;
#pragma unroll
        for (int ci = 0; ci < CIN; ci += 4) {
            const float w0 = Wk[(ci + 0) * 64 + co];
            const float w1 = Wk[(ci + 1) * 64 + co];
            const float w2 = Wk[(ci + 2) * 64 + co];
            const float w3 = Wk[(ci + 3) * 64 + co];
#pragma unroll
            for (int r = 0; r < 8; ++r) {
                const float4 s4 = *reinterpret_cast<const float4*>(&sh[rh * 8 + r][ci]);
                acc[r] = fmaf(s4.x, w0, fmaf(s4.y, w1, fmaf(s4.z, w2, fmaf(s4.w, w3, acc[r]))));
            }
        }
    }

    // write output + per-block column stats
    float s = 0.f, q = 0.f;
#pragma unroll
    for (int r = 0; r < 8; ++r) {
        const int orow = rowBase + rh * 8 + r;
        if (orow < nOut) {
            const float v = acc[r];
            out[(long long)orow * 64 + co] = v;
            s += v;
            q += v * v;
        }
    }
    if (pSum != nullptr) {
        red[0][rh][co] = s;
        red[1][rh][co] = q;
        __syncthreads();
        if (rh == 0) {
            pSum[(long long)blockIdx.x * 64 + co] = red[0][0][co] + red[0][1][co];
            pSq [(long long)blockIdx.x * 64 + co] = red[1][0][co] + red[1][1][co];
        }
    }
}

// ---------------------------------------------------------------------------
// Reduce per-block partials -> mean[64], rstd[64].  Deterministic.
// ---------------------------------------------------------------------------
__global__ void __launch_bounds__(1024)
bn_reduce_kernel(const float* __restrict__ pSum, const float* __restrict__ pSq,
                 int nBlocks, int nRows, float* __restrict__ statsOut)
{
    __shared__ float shs[1024];
    __shared__ float shq[1024];
    const int t = threadIdx.x;
    const int co = t & 63;
    const int chunk = t >> 6;     // 0..15

    float s0 = 0.f, s1 = 0.f, s2 = 0.f, s3 = 0.f;
    float q0 = 0.f, q1 = 0.f, q2 = 0.f, q3 = 0.f;
    int b = chunk;
    for (; b + 48 < nBlocks; b += 64) {
        s0 += pSum[(b +  0) * 64 + co];  q0 += pSq[(b +  0) * 64 + co];
        s1 += pSum[(b + 16) * 64 + co];  q1 += pSq[(b + 16) * 64 + co];
        s2 += pSum[(b + 32) * 64 + co];  q2 += pSq[(b + 32) * 64 + co];
        s3 += pSum[(b + 48) * 64 + co];  q3 += pSq[(b + 48) * 64 + co];
    }
    for (; b < nBlocks; b += 16) {
        s0 += pSum[b * 64 + co];  q0 += pSq[b * 64 + co];
    }
    shs[t] = (s0 + s1) + (s2 + s3);
    shq[t] = (q0 + q1) + (q2 + q3);
    __syncthreads();
    for (int off = 512; off >= 64; off >>= 1) {
        if (t < off) { shs[t] += shs[t + off]; shq[t] += shq[t + off]; }
        __syncthreads();
    }
    if (t < 64) {
        const float inv  = 1.0f / (float)nRows;
        const float mean = shs[t] * inv;
        const float var  = shq[t] * inv - mean * mean;
        statsOut[t]      = mean;
        statsOut[64 + t] = rsqrtf(var + 1e-5f);
    }
}

// ---------------------------------------------------------------------------
// x = lrelu(bn(tD)) + lrelu(bn(tB))   (residual merge)
// ---------------------------------------------------------------------------
__global__ void combine_kernel(const float* __restrict__ tD, const float* __restrict__ stD,
                               const float* __restrict__ tB, const float* __restrict__ stB,
                               float* __restrict__ x, long long total)
{
    long long i = (long long)blockIdx.x * blockDim.x + threadIdx.x;
    const long long stride = (long long)gridDim.x * blockDim.x;
    for (; i < total; i += stride) {
        const int c = (int)(i & 63);
        float a = (tD[i] - stD[c]) * stD[64 + c];
        a = a > 0.f ? a : 0.01f * a;
        float bsv = (tB[i] - stB[c]) * stB[64 + c];
        bsv = bsv > 0.f ? bsv : 0.01f * bsv;
        x[i] = a + bsv;
    }
}

// ---------------------------------------------------------------------------
// out[m] = [x1 | x2 | x3] @ down_w   (192 -> 64)
// ---------------------------------------------------------------------------
__global__ void __launch_bounds__(128)
final_kernel(const float* __restrict__ X1, const float* __restrict__ X2,
             const float* __restrict__ X3, const float* __restrict__ dw,
             float* __restrict__ out, int M)
{
    __shared__ __align__(16) float sh[ROWS][64];
    const int t = threadIdx.x, co = t & 63, rh = t >> 6;
    const int rowBase = blockIdx.x * ROWS;
    float acc[8];
#pragma unroll
    for (int r = 0; r < 8; ++r) acc[r] = 0.f;

    const float* srcs[3] = {X1, X2, X3};
    for (int s3 = 0; s3 < 3; ++s3) {
        const float* src = srcs[s3];
        __syncthreads();
#pragma unroll
        for (int i4 = t; i4 < ROWS * 64 / 4; i4 += 128) {
            const int r  = (i4 * 4) >> 6;
            const int ci = (i4 * 4) & 63;
            const int orow = rowBase + r;
            float4 v = make_float4(0.f, 0.f, 0.f, 0.f);
            if (orow < M)
                v = *reinterpret_cast<const float4*>(&src[(long long)orow * 64 + ci]);
            *reinterpret_cast<float4*>(&sh[r][ci]) = v;
        }
        __syncthreads();
        const float* Wk = dw + s3 * 64 * 64;
#pragma unroll
        for (int ci = 0; ci < 64; ci += 4) {
            const float w0 = Wk[(ci + 0) * 64 + co];
            const float w1 = Wk[(ci + 1) * 64 + co];
            const float w2 = Wk[(ci + 2) * 64 + co];
            const float w3 = Wk[(ci + 3) * 64 + co];
#pragma unroll
            for (int r = 0; r < 8; ++r) {
                const float4 s4 = *reinterpret_cast<const float4*>(&sh[rh * 8 + r][ci]);
                acc[r] = fmaf(s4.x, w0, fmaf(s4.y, w1, fmaf(s4.z, w2, fmaf(s4.w, w3, acc[r]))));
            }
        }
    }
#pragma unroll
    for (int r = 0; r < 8; ++r) {
        const int orow = rowBase + rh * 8 + r;
        if (orow < M) out[(long long)orow * 64 + co] = acc[r];
    }
}

// ---------------------------------------------------------------------------
extern "C" void kernel_launch(void* const* d_in, const int* in_sizes, int n_in,
                              void* d_out, int out_size)
{
    const float* feats   = (const float*)d_in[0];
    const float* b1_w1   = (const float*)d_in[1];
    const float* b1_w1_2 = (const float*)d_in[2];
    const float* b1_w2   = (const float*)d_in[3];
    const float* b1_w2_2 = (const float*)d_in[4];
    const float* pool_w  = (const float*)d_in[5];
    const float* b2_w1   = (const float*)d_in[6];
    const float* b2_w1_2 = (const float*)d_in[7];
    const float* b2_w2   = (const float*)d_in[8];
    const float* b2_w2_2 = (const float*)d_in[9];
    const float* b3_w1   = (const float*)d_in[10];
    const float* b3_w1_2 = (const float*)d_in[11];
    const float* b3_w2   = (const float*)d_in[12];
    const float* b3_w2_2 = (const float*)d_in[13];
    const float* down_w  = (const float*)d_in[14];
    const int* n331_1 = (const int*)d_in[15];
    const int* n313_1 = (const int*)d_in[16];
    const int* pool_n = (const int*)d_in[17];
    const int* n331_2 = (const int*)d_in[18];
    const int* n313_2 = (const int*)d_in[19];
    const int* n331_3 = (const int*)d_in[20];
    const int* n313_3 = (const int*)d_in[21];

    const int N = in_sizes[0] / 32;       // 80000
    const int M = out_size / 64;          // pooled active sites

    float *A, *B, *C, *X1, *X2, *X3, *pS, *pQ, *st;
    cudaGetSymbolAddress((void**)&A,  g_A);
    cudaGetSymbolAddress((void**)&B,  g_B);
    cudaGetSymbolAddress((void**)&C,  g_C);
    cudaGetSymbolAddress((void**)&X1, g_X1);
    cudaGetSymbolAddress((void**)&X2, g_X2);
    cudaGetSymbolAddress((void**)&X3, g_X3);
    cudaGetSymbolAddress((void**)&pS, g_pS);
    cudaGetSymbolAddress((void**)&pQ, g_pQ);
    cudaGetSymbolAddress((void**)&st, g_stats);
    float* st0 = st;
    float* st1 = st + 128;
    float* st2 = st + 256;
    float* st3 = st + 384;

    const int gN = (N + ROWS - 1) / ROWS;
    const int gM = (M + ROWS - 1) / ROWS;

    // ---- block 1 (N rows, 32 -> 64) ----
    conv_kernel<32, 9><<<gN, 128>>>(feats, N, n331_1, N, b1_w1,   nullptr, A, pS, pQ);
    bn_reduce_kernel<<<1, 1024>>>(pS, pQ, gN, N, st0);
    conv_kernel<64, 9><<<gN, 128>>>(A,     N, n313_1, N, b1_w1_2, st0,     B, pS, pQ);
    bn_reduce_kernel<<<1, 1024>>>(pS, pQ, gN, N, st1);
    conv_kernel<32, 9><<<gN, 128>>>(feats, N, n313_1, N, b1_w2,   nullptr, C, pS, pQ);
    bn_reduce_kernel<<<1, 1024>>>(pS, pQ, gN, N, st2);
    conv_kernel<64, 9><<<gN, 128>>>(C,     N, n331_1, N, b1_w2_2, st2,     A, pS, pQ);
    bn_reduce_kernel<<<1, 1024>>>(pS, pQ, gN, N, st3);
    combine_kernel<<<2048, 256>>>(A, st3, B, st1, C, (long long)N * 64);

    // ---- pool (strided SparseConv3d, K=27): C (N rows) -> X1 (M rows) ----
    conv_kernel<64, 27><<<gM, 128>>>(C, N, pool_n, M, pool_w, nullptr, X1, nullptr, nullptr);

    // ---- block 2 (M rows, dilation 2) ----
    conv_kernel<64, 9><<<gM, 128>>>(X1, M, n331_2, M, b2_w1,   nullptr, A, pS, pQ);
    bn_reduce_kernel<<<1, 1024>>>(pS, pQ, gM, M, st0);
    conv_kernel<64, 9><<<gM, 128>>>(A,  M, n313_2, M, b2_w1_2, st0,     B, pS, pQ);
    bn_reduce_kernel<<<1, 1024>>>(pS, pQ, gM, M, st1);
    conv_kernel<64, 9><<<gM, 128>>>(X1, M, n313_2, M, b2_w2,   nullptr, C, pS, pQ);
    bn_reduce_kernel<<<1, 1024>>>(pS, pQ, gM, M, st2);
    conv_kernel<64, 9><<<gM, 128>>>(C,  M, n331_2, M, b2_w2_2, st2,     A, pS, pQ);
    bn_reduce_kernel<<<1, 1024>>>(pS, pQ, gM, M, st3);
    combine_kernel<<<2048, 256>>>(A, st3, B, st1, X2, (long long)M * 64);

    // ---- block 3 (M rows, dilation 3) ----
    conv_kernel<64, 9><<<gM, 128>>>(X2, M, n331_3, M, b3_w1,   nullptr, A, pS, pQ);
    bn_reduce_kernel<<<1, 1024>>>(pS, pQ, gM, M, st0);
    conv_kernel<64, 9><<<gM, 128>>>(A,  M, n313_3, M, b3_w1_2, st0,     B, pS, pQ);
    bn_reduce_kernel<<<1, 1024>>>(pS, pQ, gM, M, st1);
    conv_kernel<64, 9><<<gM, 128>>>(X2, M, n313_3, M, b3_w2,   nullptr, C, pS, pQ);
    bn_reduce_kernel<<<1, 1024>>>(pS, pQ, gM, M, st2);
    conv_kernel<64, 9><<<gM, 128>>>(C,  M, n331_3, M, b3_w2_2, st2,     A, pS, pQ);
    bn_reduce_kernel<<<1, 1024>>>(pS, pQ, gM, M, st3);
    combine_kernel<<<2048, 256>>>(A, st3, B, st1, X3, (long long)M * 64);

    // ---- final 1x1 fuse: [X1 | X2 | X3] @ down_w ----
    final_kernel<<<gM, 128>>>(X1, X2, X3, down_w, (float*)d_out, M);
}